// round 10
// baseline (speedup 1.0000x reference)
#include <cuda_runtime.h>
#include <cuda_bf16.h>
#include <cstdint>

// Problem constants
#define NN   512
#define BB   128
#define TT   1000
#define INPD 6

#define CLSZ    8     // cluster size (CTAs)
#define NCLUST  16    // 128 batches / 8 per cluster
#define ROWS    64    // N rows per CTA
#define THREADS 512
#define WPAD    516   // padded row stride for W in smem
#define SPAD    516   // padded k-stride for batch-major state

// smem layout (floats)
#define OFF_W       0
#define OFF_SBUF    (ROWS * WPAD)                   // 33024: [2][8][516]
#define OFF_SCR     (OFF_SBUF + 2 * 8 * SPAD)       // 41280: 3 chunks * 4 rg * 32 lanes * 4 u64 = 3072 floats
#define OFF_UIN     (OFF_SCR + 3072)                // 44352 (48 used, pad 64)
#define OFF_WINP    (OFF_UIN + 64)                  // 44416 (384)
#define OFF_WOUT    (OFF_WINP + 384)                // 44800 (512)
#define SMEM_FLOATS (OFF_WOUT + 512)                // 45312
#define SMEM_BYTES  (SMEM_FLOATS * 4)               // 181248

typedef unsigned long long u64;

// global exchange buffer: [2][NCLUST][8][512] floats (batch-major per cluster)
__device__ float g_sx[2 * NCLUST * 8 * NN];

__device__ __forceinline__ u64 f2fma(u64 a, u64 b, u64 c) {
    u64 d; asm("fma.rn.f32x2 %0,%1,%2,%3;" : "=l"(d) : "l"(a), "l"(b), "l"(c)); return d;
}
__device__ __forceinline__ u64 f2add(u64 a, u64 b) {
    u64 d; asm("add.rn.f32x2 %0,%1,%2;" : "=l"(d) : "l"(a), "l"(b)); return d;
}
__device__ __forceinline__ float2 up2(u64 a) {
    float2 f; asm("mov.b64 {%0,%1},%2;" : "=f"(f.x), "=f"(f.y) : "l"(a)); return f;
}
__device__ __forceinline__ void cluster_arrive() {
    asm volatile("barrier.cluster.arrive.aligned;" ::: "memory");
}
__device__ __forceinline__ void cluster_wait() {
    asm volatile("barrier.cluster.wait.aligned;" ::: "memory");
}

__global__ void __cluster_dims__(CLSZ, 1, 1) __launch_bounds__(THREADS, 1)
rnn_kernel(const float* __restrict__ u, const float* __restrict__ rnoise,
           const float* __restrict__ inoise, const float* __restrict__ Wr,
           const float* __restrict__ Wi, const float* __restrict__ Wo,
           const float* __restrict__ y0, float* __restrict__ states,
           float* __restrict__ outputs)
{
    extern __shared__ float sm[];
    float* smW   = sm + OFF_W;      // [64][516] row-major
    float* sbuf  = sm + OFF_SBUF;   // [2][8][516] batch-major state
    u64*   scr   = (u64*)(sm + OFF_SCR);  // [3][4][32][4] u64
    float* uin   = sm + OFF_UIN;    // [6][8]
    float* winp  = sm + OFF_WINP;   // [64][6]
    float* wout  = sm + OFF_WOUT;   // [512]

    const int tid  = threadIdx.x;
    const int wid  = tid >> 5;
    const int lane = tid & 31;
    const int kc   = wid >> 2;          // K-chunk 0..3 (128 k each)
    const int rg   = wid & 3;           // row-group 0..3 (16 rows each)
    const int rl   = rg * 16 + (lane >> 1);  // local row 0..63
    const int bh   = lane & 1;          // batch half: batches bh*4 .. bh*4+3

    const int rank  = blockIdx.x & (CLSZ - 1);
    const int cl    = blockIdx.x >> 3;
    const int rbase = rank * ROWS;   // global row base
    const int bbase = cl * 8;        // global batch base

    const float ALPHA_F = 0.1f;
    const float OMA     = 0.9f;

    // ---- setup: W_rec slice, W_inp, W_out ----
    for (int idx = tid * 4; idx < ROWS * NN; idx += THREADS * 4) {
        int r = idx >> 9, k = idx & (NN - 1);
        *(float4*)(smW + r * WPAD + k) = *(const float4*)(Wr + (size_t)(rbase + r) * NN + k);
    }
    for (int idx = tid; idx < ROWS * INPD; idx += THREADS)
        winp[idx] = Wi[(size_t)rbase * INPD + idx];
    for (int idx = tid; idx < NN; idx += THREADS)
        wout[idx] = Wo[idx];
    // initial state, batch-major, parity 0
    for (int k = tid; k < NN; k += THREADS) {
        float v = y0[k];
        #pragma unroll
        for (int b = 0; b < 8; b++) sbuf[b * SPAD + k] = v;
    }
    // states[:, 0, :]
    for (int idx = tid; idx < 8 * ROWS; idx += THREADS) {
        int b = idx >> 6, r = idx & (ROWS - 1);
        __stcs(states + (size_t)(bbase + b) * TT * NN + rbase + r, y0[rbase + r]);
    }
    __syncthreads();

    // ---- main recurrence: t = 0 .. T-2 ----
    for (int t = 0; t < TT - 1; ++t) {
        const int pc = t & 1, pn = pc ^ 1;
        const float* sb = sbuf + pc * (8 * SPAD);

        // prefetch rec_noise for epilogue warps (kc==0): 4 batches
        float rnv[4];
        if (kc == 0) {
            const float* rp = rnoise + (size_t)t * NN + rbase + rl;
            #pragma unroll
            for (int j = 0; j < 4; j++)
                rnv[j] = __ldcs(rp + (size_t)(bbase + bh * 4 + j) * TT * NN);
        }
        // prefetch (u + inp_noise)
        if (wid == 4) {
            for (int idx = lane; idx < 48; idx += 32) {
                int b = idx & 7, j = idx >> 3;
                size_t gi = (size_t)(bbase + b) * TT * INPD + (size_t)t * INPD + j;
                uin[j * 8 + b] = u[gi] + inoise[gi];
            }
        }

        // ---- K-loop over this warp's 128-k chunk ----
        // acc[j] = (even-k partial, odd-k partial) for batch bh*4+j
        u64 acc0 = 0, acc1 = 0, acc2 = 0, acc3 = 0;
        {
            const float* wrow = smW + rl * WPAD + kc * 128;
            const float* sb0 = sb + (bh * 4 + 0) * SPAD + kc * 128;
            const float* sb1 = sb + (bh * 4 + 1) * SPAD + kc * 128;
            const float* sb2 = sb + (bh * 4 + 2) * SPAD + kc * 128;
            const float* sb3 = sb + (bh * 4 + 3) * SPAD + kc * 128;
            #pragma unroll 4
            for (int k = 0; k < 128; k += 4) {
                ulonglong2 w2 = *(const ulonglong2*)(wrow + k);  // (w[k],w[k+1]),(w[k+2],w[k+3])
                ulonglong2 s0 = *(const ulonglong2*)(sb0 + k);
                ulonglong2 s1 = *(const ulonglong2*)(sb1 + k);
                ulonglong2 s2 = *(const ulonglong2*)(sb2 + k);
                ulonglong2 s3 = *(const ulonglong2*)(sb3 + k);
                acc0 = f2fma(w2.x, s0.x, acc0); acc0 = f2fma(w2.y, s0.y, acc0);
                acc1 = f2fma(w2.x, s1.x, acc1); acc1 = f2fma(w2.y, s1.y, acc1);
                acc2 = f2fma(w2.x, s2.x, acc2); acc2 = f2fma(w2.y, s2.y, acc2);
                acc3 = f2fma(w2.x, s3.x, acc3); acc3 = f2fma(w2.y, s3.y, acc3);
            }
        }

        // stash partials for K-chunks 1..3
        if (kc > 0) {
            u64* sc = scr + (((kc - 1) * 4 + rg) * 32 + lane) * 4;
            ulonglong2 a; a.x = acc0; a.y = acc1;
            ulonglong2 b2; b2.x = acc2; b2.y = acc3;
            *(ulonglong2*)sc = a;
            *(ulonglong2*)(sc + 2) = b2;
        }
        __syncthreads();

        if (kc == 0) {
            // reduce 3 stashed partials
            #pragma unroll
            for (int c = 0; c < 3; c++) {
                const u64* sc = scr + ((c * 4 + rg) * 32 + lane) * 4;
                ulonglong2 qa = *(const ulonglong2*)sc;
                ulonglong2 qb = *(const ulonglong2*)(sc + 2);
                acc0 = f2add(acc0, qa.x); acc1 = f2add(acc1, qa.y);
                acc2 = f2add(acc2, qb.x); acc3 = f2add(acc3, qb.y);
            }
            float pre[4];
            { float2 q = up2(acc0); pre[0] = q.x + q.y; }
            { float2 q = up2(acc1); pre[1] = q.x + q.y; }
            { float2 q = up2(acc2); pre[2] = q.x + q.y; }
            { float2 q = up2(acc3); pre[3] = q.x + q.y; }

            // + (u + inp_noise) @ W_inp^T
            #pragma unroll
            for (int j = 0; j < INPD; j++) {
                float wij = winp[rl * INPD + j];
                const float* up = uin + j * 8 + bh * 4;
                #pragma unroll
                for (int b = 0; b < 4; b++) pre[b] += wij * up[b];
            }

            // s_new = (1-a)*s + a*(relu(pre) + rn)
            float sn[4];
            #pragma unroll
            for (int b = 0; b < 4; b++) {
                float sold = sb[(bh * 4 + b) * SPAD + rbase + rl];
                float v = fmaxf(pre[b], 0.0f) + rnv[b];
                sn[b] = OMA * sold + ALPHA_F * v;
            }

            // publish slice (batch-major) + states output
            float* dg = g_sx + ((size_t)pn * NCLUST + cl) * (8 * NN) + rbase + rl;
            #pragma unroll
            for (int b = 0; b < 4; b++) {
                dg[(bh * 4 + b) * NN] = sn[b];
                __stcs(states + (size_t)(bbase + bh * 4 + b) * TT * NN + (size_t)(t + 1) * NN + rbase + rl, sn[b]);
            }
        } else if (wid == 15) {
            // outputs[bbase+rank, t] = dot(s_t, W_out)  (batch-major state: contiguous)
            const float* sr = sb + rank * SPAD;
            float v = 0.0f;
            #pragma unroll
            for (int i = 0; i < 16; i++) {
                int k = lane + 32 * i;
                v += sr[k] * wout[k];
            }
            #pragma unroll
            for (int off = 16; off; off >>= 1) v += __shfl_xor_sync(0xffffffffu, v, off);
            if (lane == 0) outputs[(size_t)(bbase + rank) * TT + t] = v;
        }

        // release our slice, acquire everyone's
        cluster_arrive();
        cluster_wait();

        // refill full next-state (batch-major) into local smem
        {
            const float4* src = (const float4*)(g_sx + ((size_t)pn * NCLUST + cl) * (8 * NN));
            float* dstb = sbuf + pn * (8 * SPAD);
            #pragma unroll
            for (int it = 0; it < 2; it++) {
                int i = tid + it * THREADS;       // 0..1023 float4 index
                int b = i >> 7, k4 = i & 127;
                *(float4*)(dstb + b * SPAD + k4 * 4) = __ldcg(src + i);
            }
        }
        __syncthreads();
    }

    // final output: outputs[:, T-1] from s_{T-1} (parity 1)
    if (wid == 15) {
        const float* sr = sbuf + ((TT - 1) & 1) * (8 * SPAD) + rank * SPAD;
        float v = 0.0f;
        #pragma unroll
        for (int i = 0; i < 16; i++) {
            int k = lane + 32 * i;
            v += sr[k] * wout[k];
        }
        #pragma unroll
        for (int off = 16; off; off >>= 1) v += __shfl_xor_sync(0xffffffffu, v, off);
        if (lane == 0) outputs[(size_t)(bbase + rank) * TT + (TT - 1)] = v;
    }
}

extern "C" void kernel_launch(void* const* d_in, const int* in_sizes, int n_in,
                              void* d_out, int out_size)
{
    const float* u      = (const float*)d_in[0];
    const float* rnoise = (const float*)d_in[1];
    const float* inoise = (const float*)d_in[2];
    const float* Wr     = (const float*)d_in[3];
    const float* Wi     = (const float*)d_in[4];
    const float* Wo     = (const float*)d_in[5];
    const float* y0     = (const float*)d_in[6];

    float* states  = (float*)d_out;
    float* outputs = states + (size_t)BB * TT * NN;

    cudaFuncSetAttribute(rnn_kernel, cudaFuncAttributeMaxDynamicSharedMemorySize, SMEM_BYTES);
    rnn_kernel<<<NCLUST * CLSZ, THREADS, SMEM_BYTES>>>(u, rnoise, inoise, Wr, Wi, Wo, y0,
                                                       states, outputs);
}